// round 2
// baseline (speedup 1.0000x reference)
#include <cuda_runtime.h>
#include <stdint.h>

// Problem shape (fixed by the reference): x is (T, B, 1) fp32, lr scalar.
#define T_DIM 8192
#define B_DIM 4096
#define S_CHUNKS 64
#define CH 128          // T_DIM / S_CHUNKS
#define NWORDS 4        // CH / 32
#define B2 (B_DIM / 2)  // column-pairs

// Scratch (device globals — no allocation allowed).
__device__ float4 g_coef [S_CHUNKS * B_DIM];  // (A0, C0, A1, C1) per (s,b)    4 MB
__device__ uint4  g_bits [S_CHUNKS * B_DIM];  // 128 packed x bits per (s,b)   4 MB
__device__ float2 g_xprev[S_CHUNKS * B2];     // x[t0-1] per (s, col-pair)     1 MB
__device__ float2 g_state[S_CHUNKS * B_DIM];  // (p0,p1) entering chunk        2 MB

__device__ __forceinline__ float clamp_lr(const float* lrp) {
    return fminf(fmaxf(*lrp, 0.0f), 1.0f);
}

// ---------------------------------------------------------------------------
// Pass 1: per (chunk s, column-pair) — read x chunk once (float2), emit packed
// bits + affine chunk composition. Since each step updates exactly one state
// (selected by obs_prev = x_{t-1}), the multiplier A is r^(#updates), obtained
// by POPCOUNT of the obs_prev bit stream + a shared r^k table (table built by
// sequential FMUL so rounding matches a sequential product). Only the C term
// needs per-step FMA:  pb==0: C0 = C0*r + lr*x_t ; pb==1: C1 = C1*r + lr*x_t.
// ---------------------------------------------------------------------------
__global__ void __launch_bounds__(128) pass1_kernel(
    const float2* __restrict__ x2, const float* __restrict__ lrp)
{
    __shared__ float rpow[CH + 1];
    const float lr = clamp_lr(lrp);
    const float r  = 1.0f - lr;
    if (threadIdx.x == 0) {
        float a = 1.0f; rpow[0] = 1.0f;
        #pragma unroll 1
        for (int k = 1; k <= CH; k++) { a *= r; rpow[k] = a; }
    }
    __syncthreads();

    const int b2 = blockIdx.x * 128 + threadIdx.x;   // [0, B2)
    const int s  = blockIdx.y;
    const float2* xp = x2 + (size_t)(s * CH) * B2 + b2;

    float2 xprev = make_float2(0.f, 0.f);
    if (s > 0) xprev = xp[-(ptrdiff_t)B2];
    g_xprev[s * B2 + b2] = xprev;

    bool  pb[2] = { xprev.x != 0.f, xprev.y != 0.f };
    float C0[2] = { 0.f, 0.f }, C1[2] = { 0.f, 0.f };
    uint32_t W[2][NWORDS];

    #pragma unroll
    for (int wi = 0; wi < NWORDS; wi++) {
        uint32_t w[2] = { 0u, 0u };
        #pragma unroll
        for (int i0 = 0; i0 < 32; i0 += 8) {
            float2 xv[8];
            #pragma unroll
            for (int j = 0; j < 8; j++)
                xv[j] = xp[(size_t)(wi * 32 + i0 + j) * B2];
            #pragma unroll
            for (int j = 0; j < 8; j++) {
                const uint32_t bit = 1u << (i0 + j);
                const float v[2] = { xv[j].x, xv[j].y };
                #pragma unroll
                for (int c = 0; c < 2; c++) {
                    const bool  xb = (v[c] != 0.0f);
                    const float t  = v[c] * lr;              // exact: x in {0,1}
                    const float n0 = fmaf(C0[c], r, t);
                    const float n1 = fmaf(C1[c], r, t);
                    C0[c] = pb[c] ? C0[c] : n0;
                    C1[c] = pb[c] ? n1    : C1[c];
                    if (xb) w[c] |= bit;                     // predicated LOP
                    pb[c] = xb;
                }
            }
        }
        W[0][wi] = w[0];
        W[1][wi] = w[1];
    }

    const float xpv[2] = { xprev.x, xprev.y };
    #pragma unroll
    for (int c = 0; c < 2; c++) {
        // obs_prev stream over the chunk = [xprev, x_0 .. x_126]
        const int ones = __popc(W[c][0]) + __popc(W[c][1])
                       + __popc(W[c][2]) + __popc(W[c][3]);
        const int n1 = ones - (int)(W[c][3] >> 31) + (xpv[c] != 0.f ? 1 : 0);
        g_coef[s * B_DIM + 2 * b2 + c] =
            make_float4(rpow[CH - n1], C0[c], rpow[n1], C1[c]);
        g_bits[s * B_DIM + 2 * b2 + c] =
            make_uint4(W[c][0], W[c][1], W[c][2], W[c][3]);
    }
}

// ---------------------------------------------------------------------------
// Scan: one thread per column; 64 sequential affine compositions (all data
// L2-resident right after pass1). Stores the (p0,p1) state entering each chunk.
// ---------------------------------------------------------------------------
__global__ void __launch_bounds__(256) scan_kernel()
{
    const int b = blockIdx.x * blockDim.x + threadIdx.x;
    float p0 = 0.5f, p1 = 0.5f;
    #pragma unroll 16
    for (int s = 0; s < S_CHUNKS; s++) {
        const float4 c = g_coef[s * B_DIM + b];
        g_state[s * B_DIM + b] = make_float2(p0, p1);
        p0 = fmaf(p0, c.x, c.y);
        p1 = fmaf(p1, c.z, c.w);
    }
}

// ---------------------------------------------------------------------------
// Pass 2: replay each chunk from its stored entry state using the packed bits
// (x never re-read from HBM; scratch comes from L2). float2 stores.
// ---------------------------------------------------------------------------
__global__ void __launch_bounds__(128) pass2_kernel(
    float2* __restrict__ out2, const float* __restrict__ lrp)
{
    const int b2 = blockIdx.x * 128 + threadIdx.x;
    const int s  = blockIdx.y;
    const float lr = clamp_lr(lrp);

    float2* op = out2 + (size_t)(s * CH) * B2 + b2;

    // (p0,p1) for the 2 columns = one float4 load
    const float4 st = reinterpret_cast<const float4*>(g_state)
                        [(size_t)s * (B_DIM / 2) + b2];
    float p0[2] = { st.x, st.z };
    float p1[2] = { st.y, st.w };

    uint32_t W[2][NWORDS];
    #pragma unroll
    for (int c = 0; c < 2; c++) {
        const uint4 t = g_bits[s * B_DIM + 2 * b2 + c];
        W[c][0] = t.x; W[c][1] = t.y; W[c][2] = t.z; W[c][3] = t.w;
    }

    const float2 xprev = g_xprev[s * B2 + b2];
    bool pb[2] = { xprev.x != 0.f, xprev.y != 0.f };

    #pragma unroll
    for (int wi = 0; wi < NWORDS; wi++) {
        #pragma unroll
        for (int i = 0; i < 32; i++) {
            float ov[2];
            #pragma unroll
            for (int c = 0; c < 2; c++) {
                const bool  xb = (W[c][wi] >> i) & 1u;       // immediate-mask pred
                const float xv = xb ? 1.0f : 0.0f;
                const float pa = pb[c] ? p1[c] : p0[c];      // state being updated
                const float u  = fmaf(lr, xv - pa, pa);
                p0[c] = pb[c] ? p0[c] : u;
                p1[c] = pb[c] ? u     : p1[c];
                ov[c] = xb ? p1[c] : p0[c];                  // pred = selected state
                pb[c] = xb;
            }
            op[(size_t)(wi * 32 + i) * B2] = make_float2(ov[0], ov[1]);
        }
    }
}

extern "C" void kernel_launch(void* const* d_in, const int* in_sizes, int n_in,
                              void* d_out, int out_size)
{
    const float* x  = (const float*)d_in[0];
    const float* lr = (const float*)d_in[1];
    if (n_in >= 2 && in_sizes[0] == 1) { x = (const float*)d_in[1]; lr = (const float*)d_in[0]; }

    dim3 blk(128);
    dim3 grid_pass(B2 / 128, S_CHUNKS);   // (16, 64) = 1024 blocks, 131072 threads

    pass1_kernel<<<grid_pass, blk>>>((const float2*)x, lr);
    scan_kernel<<<B_DIM / 256, dim3(256)>>>();
    pass2_kernel<<<grid_pass, blk>>>((float2*)d_out, lr);
}

// round 3
// speedup vs baseline: 1.0552x; 1.0552x over previous
#include <cuda_runtime.h>
#include <stdint.h>

// Problem shape (fixed by the reference): x is (T, B, 1) fp32, lr scalar.
#define T_DIM 8192
#define B_DIM 4096
#define S_CHUNKS 64
#define CH 128          // T_DIM / S_CHUNKS
#define NWORDS 4        // CH / 32

// Scratch (device globals — no allocation allowed).
__device__ float2 g_coef0[S_CHUNKS * B_DIM];  // (A0, C0) per (s,b)   2 MB
__device__ float2 g_coef1[S_CHUNKS * B_DIM];  // (A1, C1) per (s,b)   2 MB
__device__ uint4  g_bits [S_CHUNKS * B_DIM];  // 128 packed x bits    4 MB
__device__ float  g_xprev[S_CHUNKS * B_DIM];  // x[t0-1]              1 MB
__device__ float  g_st0  [S_CHUNKS * B_DIM];  // p0 entering chunk    1 MB
__device__ float  g_st1  [S_CHUNKS * B_DIM];  // p1 entering chunk    1 MB

__device__ __forceinline__ float clamp_lr(const float* lrp) {
    return fminf(fmaxf(*lrp, 0.0f), 1.0f);
}

// r^n for n in [0,255] by square-and-multiply (no smem, no sync).
__device__ __forceinline__ float rpow_int(float r, int n) {
    float res = 1.0f, base = r;
    #pragma unroll
    for (int i = 0; i < 8; i++) {
        res  = ((n >> i) & 1) ? res * base : res;
        base = base * base;
    }
    return res;
}

// ---------------------------------------------------------------------------
// Pass 1: per (chunk s, column b). One column per thread (keeps 55 warps/SM).
// Each step updates exactly one state (chosen by obs_prev = x_{t-1}), so the
// chunk multiplier is r^(#updates) — obtained by POPCOUNT of the obs_prev bit
// stream. Only the additive term C needs per-step work:
//   pb==0: C0 = C0*r + lr*x_t    pb==1: C1 = C1*r + lr*x_t
// Inner loop ~6 SASS: FSETP, FMUL, 2 predicated FFMA (ternary, dst==src),
// predicated LOP (bit set), predicate move.
// ---------------------------------------------------------------------------
__global__ void __launch_bounds__(256) pass1_kernel(
    const float* __restrict__ x, const float* __restrict__ lrp)
{
    const int b = blockIdx.x * blockDim.x + threadIdx.x;
    const int s = blockIdx.y;
    const float lr = clamp_lr(lrp);
    const float r  = 1.0f - lr;

    const float* xp = x + (size_t)(s * CH) * B_DIM + b;

    const float xprev = (s == 0) ? 0.0f : xp[-(ptrdiff_t)B_DIM];
    g_xprev[s * B_DIM + b] = xprev;
    bool pb = (xprev != 0.0f);

    float C0 = 0.0f, C1 = 0.0f;
    uint32_t W[NWORDS];

    #pragma unroll
    for (int wi = 0; wi < NWORDS; wi++) {
        uint32_t w = 0;
        #pragma unroll
        for (int i0 = 0; i0 < 32; i0 += 8) {
            float xv[8];                               // 8-deep LDG batch (MLP)
            #pragma unroll
            for (int j = 0; j < 8; j++)
                xv[j] = xp[(size_t)(wi * 32 + i0 + j) * B_DIM];
            #pragma unroll
            for (int j = 0; j < 8; j++) {
                const float v  = xv[j];
                const bool  xb = (v != 0.0f);
                const float t  = v * lr;               // exact: x in {0,1}
                C0 = pb ? C0 : fmaf(C0, r, t);         // @!pb FFMA
                C1 = pb ? fmaf(C1, r, t) : C1;         // @pb  FFMA
                w  = xb ? (w | (1u << (i0 + j))) : w;  // @xb  LOP
                pb = xb;
            }
        }
        W[wi] = w;
    }

    // obs_prev stream over the chunk = [xprev, x_0 .. x_126]
    const int ones = __popc(W[0]) + __popc(W[1]) + __popc(W[2]) + __popc(W[3]);
    const int n1   = ones - (int)(W[3] >> 31) + (pb && false ? 0 : (xprev != 0.f ? 1 : 0));

    g_coef0[s * B_DIM + b] = make_float2(rpow_int(r, CH - n1), C0);
    g_coef1[s * B_DIM + b] = make_float2(rpow_int(r, n1),      C1);
    g_bits [s * B_DIM + b] = make_uint4(W[0], W[1], W[2], W[3]);
}

// ---------------------------------------------------------------------------
// Scan: p0 and p1 lineages are independent -> 2*B threads, one lineage each.
// 64 sequential affine compositions (coef data is L2-resident after pass1).
// ---------------------------------------------------------------------------
__global__ void __launch_bounds__(256) scan_kernel()
{
    const int tid = blockIdx.x * blockDim.x + threadIdx.x;   // [0, 2*B)
    const int b   = tid & (B_DIM - 1);
    const float2* coef = (tid < B_DIM) ? g_coef0 : g_coef1;
    float*        st   = (tid < B_DIM) ? g_st0   : g_st1;

    float p = 0.5f;
    #pragma unroll 16
    for (int s = 0; s < S_CHUNKS; s++) {
        const float2 c = coef[s * B_DIM + b];
        st[s * B_DIM + b] = p;
        p = fmaf(p, c.x, c.y);
    }
}

// ---------------------------------------------------------------------------
// Pass 2: replay each chunk from its entry state using the packed bits
// (x never re-read from HBM). One column per thread. Single-FMA step:
//   u = fmaf(r, pa, xb ? lr : 0)  ==  (1-lr)*pa + lr*x_t
// ---------------------------------------------------------------------------
__global__ void __launch_bounds__(256) pass2_kernel(
    float* __restrict__ out, const float* __restrict__ lrp)
{
    const int b = blockIdx.x * blockDim.x + threadIdx.x;
    const int s = blockIdx.y;
    const float lr = clamp_lr(lrp);
    const float r  = 1.0f - lr;

    float* op = out + (size_t)(s * CH) * B_DIM + b;

    float p0 = g_st0[s * B_DIM + b];
    float p1 = g_st1[s * B_DIM + b];
    const uint4 bw = g_bits[s * B_DIM + b];
    const uint32_t W[NWORDS] = { bw.x, bw.y, bw.z, bw.w };
    bool pb = (g_xprev[s * B_DIM + b] != 0.0f);

    #pragma unroll
    for (int wi = 0; wi < NWORDS; wi++) {
        const uint32_t w = W[wi];
        #pragma unroll
        for (int i = 0; i < 32; i++) {
            const bool  xb  = (w >> i) & 1u;
            const float add = xb ? lr : 0.0f;
            const float pa  = pb ? p1 : p0;
            const float u   = fmaf(r, pa, add);
            p0 = pb ? p0 : u;
            p1 = pb ? u  : p1;
            op[(size_t)(wi * 32 + i) * B_DIM] = xb ? p1 : p0;
            pb = xb;
        }
    }
}

extern "C" void kernel_launch(void* const* d_in, const int* in_sizes, int n_in,
                              void* d_out, int out_size)
{
    const float* x  = (const float*)d_in[0];
    const float* lr = (const float*)d_in[1];
    if (n_in >= 2 && in_sizes[0] == 1) { x = (const float*)d_in[1]; lr = (const float*)d_in[0]; }

    dim3 blk(256);
    dim3 grid_pass(B_DIM / 256, S_CHUNKS);   // (16, 64), 262144 threads

    pass1_kernel<<<grid_pass, blk>>>(x, lr);
    scan_kernel<<<(2 * B_DIM) / 256, blk>>>();
    pass2_kernel<<<grid_pass, blk>>>((float*)d_out, lr);
}

// round 4
// speedup vs baseline: 1.0890x; 1.0320x over previous
#include <cuda_runtime.h>
#include <stdint.h>

// Problem shape (fixed by the reference): x is (T, B, 1) fp32, lr scalar.
#define T_DIM 8192
#define B_DIM 4096
#define S_CHUNKS 64
#define CH 128          // T_DIM / S_CHUNKS
#define NWORDS 4        // CH / 32

// Scratch (device globals — no allocation allowed). Chunk-major, coalesced over b.
__device__ float4 g_coef [S_CHUNKS * B_DIM];  // (A0, C0, A1, C1) per (s,b)   4 MB
__device__ uint4  g_bits [S_CHUNKS * B_DIM];  // 128 packed x bits per (s,b)  4 MB
__device__ float  g_xprev[S_CHUNKS * B_DIM];  // x[t0-1] per (s,b)            1 MB
__device__ float2 g_state[S_CHUNKS * B_DIM];  // (p0,p1) entering chunk       2 MB

__device__ __forceinline__ float clamp_lr(const float* lrp) {
    return fminf(fmaxf(*lrp, 0.0f), 1.0f);
}

// r^n for n in [0,255] by square-and-multiply (no smem, no syncs).
__device__ __forceinline__ float rpow_int(float r, int n) {
    float res = 1.0f, base = r;
    #pragma unroll
    for (int i = 0; i < 8; i++) {
        res  = ((n >> i) & 1) ? res * base : res;
        base = base * base;
    }
    return res;
}

// ---------------------------------------------------------------------------
// Pass 1: per (chunk s, column b), one column per thread (~55 warps/SM).
// DEPTH-16 load batches: 16 independent LDGs issued before any consumption,
// doubling bytes-in-flight per warp vs R1/R3 (the measured limiter).
// Chunk multiplier A = r^(#updates) via POPCOUNT of the obs_prev bit stream;
// only the additive C term needs per-step FMA.
// ---------------------------------------------------------------------------
__global__ void __launch_bounds__(256) pass1_kernel(
    const float* __restrict__ x, const float* __restrict__ lrp)
{
    const int b = blockIdx.x * blockDim.x + threadIdx.x;
    const int s = blockIdx.y;
    const float lr = clamp_lr(lrp);
    const float r  = 1.0f - lr;

    const float* xp = x + (size_t)(s * CH) * B_DIM + b;

    const float xprev = (s == 0) ? 0.0f : xp[-(ptrdiff_t)B_DIM];
    g_xprev[s * B_DIM + b] = xprev;
    bool pb = (xprev != 0.0f);

    float C0 = 0.0f, C1 = 0.0f;
    uint32_t W[NWORDS];

    #pragma unroll
    for (int h = 0; h < CH / 32; h++) {           // 4 words
        uint32_t w = 0;
        #pragma unroll
        for (int i0 = 0; i0 < 32; i0 += 16) {     // two 16-deep batches per word
            float xv[16];
            #pragma unroll
            for (int j = 0; j < 16; j++)
                xv[j] = xp[(size_t)(h * 32 + i0 + j) * B_DIM];
            #pragma unroll
            for (int j = 0; j < 16; j++) {
                const float v  = xv[j];
                const bool  xb = (v != 0.0f);
                const float t  = v * lr;              // exact: x in {0,1}
                C0 = pb ? C0 : fmaf(C0, r, t);        // @!pb FFMA
                C1 = pb ? fmaf(C1, r, t) : C1;        // @pb  FFMA
                w  = xb ? (w | (1u << (i0 + j))) : w; // @xb  LOP
                pb = xb;
            }
        }
        W[h] = w;
    }

    // obs_prev stream over the chunk = [xprev, x_0 .. x_126]
    const int ones = __popc(W[0]) + __popc(W[1]) + __popc(W[2]) + __popc(W[3]);
    const int n1   = ones - (int)(W[3] >> 31) + (xprev != 0.0f ? 1 : 0);

    g_coef[s * B_DIM + b] = make_float4(rpow_int(r, CH - n1), C0,
                                        rpow_int(r, n1),      C1);
    g_bits[s * B_DIM + b] = make_uint4(W[0], W[1], W[2], W[3]);
}

// ---------------------------------------------------------------------------
// Scan (R1 form): one thread per column; 64 sequential affine compositions,
// coef data L2-resident after pass1. Stores (p0,p1) entering each chunk.
// ---------------------------------------------------------------------------
__global__ void __launch_bounds__(256) scan_kernel()
{
    const int b = blockIdx.x * blockDim.x + threadIdx.x;
    float p0 = 0.5f, p1 = 0.5f;
    #pragma unroll 8
    for (int s = 0; s < S_CHUNKS; s++) {
        const float4 c = g_coef[s * B_DIM + b];
        g_state[s * B_DIM + b] = make_float2(p0, p1);
        p0 = fmaf(p0, c.x, c.y);
        p1 = fmaf(p1, c.z, c.w);
    }
}

// ---------------------------------------------------------------------------
// Pass 2 (R1 form, fastest measured): replay each chunk from its stored entry
// state using the packed bits; x never re-read from HBM.
// ---------------------------------------------------------------------------
__global__ void __launch_bounds__(256) pass2_kernel(
    float* __restrict__ out, const float* __restrict__ lrp)
{
    const int b = blockIdx.x * blockDim.x + threadIdx.x;
    const int s = blockIdx.y;
    const float lr = clamp_lr(lrp);

    float* op = out + (size_t)(s * CH) * B_DIM + b;

    const float2 st = g_state[s * B_DIM + b];
    float p0 = st.x, p1 = st.y;
    const uint4 bw = g_bits[s * B_DIM + b];
    const uint32_t W[NWORDS] = { bw.x, bw.y, bw.z, bw.w };
    bool pb = (g_xprev[s * B_DIM + b] != 0.0f);

    #pragma unroll
    for (int wi = 0; wi < NWORDS; wi++) {
        uint32_t w = W[wi];
        #pragma unroll
        for (int i = 0; i < 32; i++) {
            const bool  xb = (w & 1u);
            w >>= 1;
            const float xv = xb ? 1.0f : 0.0f;
            const float l0 = pb ? 0.0f : lr;
            const float l1 = pb ? lr   : 0.0f;
            p0 = fmaf(l0, xv - p0, p0);
            p1 = fmaf(l1, xv - p1, p1);
            op[(size_t)(wi * 32 + i) * B_DIM] = xb ? p1 : p0;
            pb = xb;
        }
    }
}

extern "C" void kernel_launch(void* const* d_in, const int* in_sizes, int n_in,
                              void* d_out, int out_size)
{
    const float* x  = (const float*)d_in[0];
    const float* lr = (const float*)d_in[1];
    if (n_in >= 2 && in_sizes[0] == 1) { x = (const float*)d_in[1]; lr = (const float*)d_in[0]; }

    dim3 blk(256);
    dim3 grid_pass(B_DIM / 256, S_CHUNKS);   // (16, 64), 262144 threads

    pass1_kernel<<<grid_pass, blk>>>(x, lr);
    scan_kernel<<<B_DIM / 256, blk>>>();
    pass2_kernel<<<grid_pass, blk>>>((float*)d_out, lr);
}